// round 15
// baseline (speedup 1.0000x reference)
#include <cuda_runtime.h>
#include <cstdint>
#include <math.h>

#define Bq 2
#define Lq 1024
#define Aq 14
#define Kq 30
#define EFq 128
#define EDGE_INq 3152
#define Mrows (Bq*Lq*Kq)      // 61440
#define BM 128
#define NCHUNK 99             // padded K = 3168

typedef uint32_t u32;

// ---- scratch ----
__device__ int g_Eidx[Mrows];
__device__ __align__(16) float g_X2[Bq*Lq*Aq*3];
__device__ __align__(16) float g_Wfrag[NCHUNK*4096];  // fragment-ordered tf32 W

__constant__ float c_freq[8] = {
    1.0f, 0.31622776601683794f, 0.1f, 0.031622776601683794f,
    0.01f, 0.0031622776601683794f, 0.001f, 0.00031622776601683794f
};

__device__ __forceinline__ u32 f2tf32(float v) {
    u32 u; asm("cvt.rna.tf32.f32 %0, %1;" : "=r"(u) : "f"(v)); return u;
}
__device__ __forceinline__ float ex2f(float x) {
    float r; asm("ex2.approx.f32 %0, %1;" : "=f"(r) : "f"(x)); return r;
}
__device__ __forceinline__ u32 smem_u32(const void* p) {
    u32 a; asm("{ .reg .u64 t; cvta.to.shared.u64 t, %1; cvt.u32.u64 %0, t; }"
               : "=r"(a) : "l"(p));
    return a;
}
__device__ __forceinline__ void mma_tf32(float* d, const u32* a, u32 b0, u32 b1) {
    asm volatile("mma.sync.aligned.m16n8k8.row.col.f32.tf32.tf32.f32 "
        "{%0,%1,%2,%3}, {%4,%5,%6,%7}, {%8,%9}, {%0,%1,%2,%3};"
        : "+f"(d[0]), "+f"(d[1]), "+f"(d[2]), "+f"(d[3])
        : "r"(a[0]), "r"(a[1]), "r"(a[2]), "r"(a[3]), "r"(b0), "r"(b1));
}
#define LDS128(v, addr) asm volatile("ld.shared.v4.f32 {%0,%1,%2,%3}, [%4];" \
    : "=f"(v.x), "=f"(v.y), "=f"(v.z), "=f"(v.w) : "r"(addr))
#define STS128(addr, a0, a1, a2, a3) asm volatile( \
    "st.shared.v4.b32 [%0], {%1,%2,%3,%4};" \
    :: "r"(addr), "r"(a0), "r"(a1), "r"(a2), "r"(a3) : "memory")
#define MBARRIER_INIT(a,c) asm volatile( \
    "mbarrier.init.shared.b64 [%0], %1;" :: "r"(a), "r"(c) : "memory")
#define MBARRIER_EXPECT_TX(a,b) asm volatile( \
    "mbarrier.arrive.expect_tx.shared.b64 _, [%0], %1;" :: "r"(a), "r"(b) : "memory")
#define CP_BULK(dst, src, mbar) asm volatile( \
    "cp.async.bulk.shared::cta.global.mbarrier::complete_tx::bytes [%0], [%1], %2, [%3];" \
    :: "r"(dst), "l"(src), "r"(16384), "r"(mbar) : "memory")
#define MBAR_WAIT(a, ph) asm volatile("{\n\t.reg .pred P;\n\tWL_%=:\n\t" \
    "mbarrier.try_wait.parity.acquire.cta.shared::cta.b64 P, [%0], %1, 0x989680;\n\t" \
    "@!P bra WL_%=;\n\t}" :: "r"(a), "r"(ph) : "memory")
#define BAR_SYNC(id, cnt)   asm volatile("bar.sync %0, %1;"   :: "r"(id), "r"(cnt) : "memory")
#define BAR_ARRIVE(id, cnt) asm volatile("bar.arrive %0, %1;" :: "r"(id), "r"(cnt) : "memory")

// =====================================================================
// Kernel 1 (merged prep): topk | prepW | buildX2   (unchanged)
// =====================================================================
#define TOPK_BLOCKS  (Bq*Lq)                 // 2048
#define PREPW_BLOCKS ((NCHUNK*4096)/256)     // 1584
#define BX2_BLOCKS   8
#define PREP_GRID    (TOPK_BLOCKS + PREPW_BLOCKS + BX2_BLOCKS)

__global__ void prep_kernel(const float* __restrict__ X,
                            const float* __restrict__ mask,
                            const float* __restrict__ W,
                            float* __restrict__ out_tail) {
    __shared__ float Da[Lq];
    __shared__ float svals[8];
    __shared__ int   sidx[8];
    __shared__ float sDmax;

    int bid = blockIdx.x;
    int tid = threadIdx.x;

    if (bid >= TOPK_BLOCKS) {
        if (bid < TOPK_BLOCKS + PREPW_BLOCKS) {
            int t = (bid - TOPK_BLOCKS) * 256 + tid;
            int e    = t & 3;
            int lane = (t >> 2) & 31;
            int q    = (t >> 7) & 3;
            int s    = (t >> 9) & 3;
            int wn   = (t >> 11) & 1;
            int k    = t >> 12;
            int nt   = 2*q + (e >> 1);
            int half = e & 1;
            int n = wn*64 + nt*8 + (lane >> 2);
            int c = k*32 + s*8 + (lane & 3) + half*4;
            float v = (c < EDGE_INq) ? W[(size_t)n * EDGE_INq + c] : 0.f;
            g_Wfrag[t] = __uint_as_float(f2tf32(v));
        } else {
            int t = (bid - TOPK_BLOCKS - PREPW_BLOCKS) * 256 + tid;
            if (t < Bq * Lq) {
                const float* xr = X + (size_t)t * Aq * 3;
                float* o = g_X2 + (size_t)t * Aq * 3;
                #pragma unroll
                for (int a = 0; a < Aq*3; a++) o[a] = xr[a];
                float Nx = xr[0],  Ny = xr[1],  Nz = xr[2];
                float Cax= xr[3],  Cay= xr[4],  Caz= xr[5];
                float Cx = xr[6],  Cy = xr[7],  Cz = xr[8];
                float bx = Cax - Nx, by = Cay - Ny, bz = Caz - Nz;
                float cx = Cx - Cax, cy = Cy - Cay, cz = Cz - Caz;
                float ax = by*cz - bz*cy;
                float ay = bz*cx - bx*cz;
                float az = bx*cy - by*cx;
                o[12] = -0.58273431f*ax + 0.56802827f*bx - 0.54067466f*cx + Cax;
                o[13] = -0.58273431f*ay + 0.56802827f*by - 0.54067466f*cy + Cay;
                o[14] = -0.58273431f*az + 0.56802827f*bz - 0.54067466f*cz + Caz;
            }
        }
        return;
    }

    int bi  = bid;
    int b   = bi >> 10;
    int i   = bi & (Lq - 1);

    const float* Xb = X + (size_t)b * Lq * Aq * 3;
    float cx = Xb[(i*Aq+1)*3+0];
    float cy = Xb[(i*Aq+1)*3+1];
    float cz = Xb[(i*Aq+1)*3+2];
    float mi = mask[b*Lq + i];

    float lmax = 0.f;
    for (int j = tid; j < Lq; j += 256) {
        float dx = cx - Xb[(j*Aq+1)*3+0];
        float dy = cy - Xb[(j*Aq+1)*3+1];
        float dz = cz - Xb[(j*Aq+1)*3+2];
        float m2 = mi * mask[b*Lq + j];
        float D  = m2 * sqrtf(dx*dx + dy*dy + dz*dz + 1e-6f);
        Da[j] = D;
        lmax = fmaxf(lmax, D);
    }
    #pragma unroll
    for (int off = 16; off; off >>= 1)
        lmax = fmaxf(lmax, __shfl_xor_sync(0xffffffffu, lmax, off));
    if ((tid & 31) == 0) svals[tid >> 5] = lmax;
    __syncthreads();
    if (tid == 0) {
        float m = svals[0];
        for (int w = 1; w < 8; w++) m = fmaxf(m, svals[w]);
        sDmax = m;
    }
    __syncthreads();
    float Dmax = sDmax;
    for (int j = tid; j < Lq; j += 256) {
        float m2 = mi * mask[b*Lq + j];
        Da[j] += 2.f * (1.f - m2) * Dmax;
    }
    __syncthreads();

    for (int k = 0; k < Kq; k++) {
        float bv = 3.4e38f; int bj = 0x7fffffff;
        for (int j = tid; j < Lq; j += 256) {
            float v = Da[j];
            if (v < bv) { bv = v; bj = j; }
        }
        #pragma unroll
        for (int off = 16; off; off >>= 1) {
            float ov = __shfl_down_sync(0xffffffffu, bv, off);
            int   oj = __shfl_down_sync(0xffffffffu, bj, off);
            if (ov < bv || (ov == bv && oj < bj)) { bv = ov; bj = oj; }
        }
        if ((tid & 31) == 0) { svals[tid >> 5] = bv; sidx[tid >> 5] = bj; }
        __syncthreads();
        if (tid == 0) {
            for (int w = 1; w < 8; w++) {
                float v = svals[w]; int jj = sidx[w];
                if (v < bv || (v == bv && jj < bj)) { bv = v; bj = jj; }
            }
            int orow = bi * Kq + k;
            g_Eidx[orow] = bj;
            if (out_tail) out_tail[orow] = (float)bj;
            Da[bj] = 3.4e38f;
        }
        __syncthreads();
    }
}

// =====================================================================
// Kernel 2: warp-specialized fused kernel.
// 384 threads: warps 0-7 consumers (pure MMA), warps 8-11 producers
// (featuregen + B bulk copies). Handoff via named barriers:
//   ready[b] = id 1+b (producers arrive, consumers sync)
//   free[b]  = id 3+b (consumers arrive, producers sync)
// afr double-buffered; B triple-buffered with per-buffer mbarrier.
// =====================================================================
#define SM_SBF   0          // 3 * 16384 = 49152
#define SM_AFR   49152      // 2 * 16384 = 32768
#define SM_MBAR  81920      // 3 x 8B
#define SM_TOTAL 82048
#define ESTRIDE  132        // epilogue reuses bytes [0, 33792)

#define CONSUME(BB, AB) do {                                                 \
    _Pragma("unroll")                                                        \
    for (int s = 0; s < 4; s++) {                                            \
        u32 afr[2][4];                                                       \
        _Pragma("unroll")                                                    \
        for (int mt = 0; mt < 2; mt++) {                                     \
            float4 av;                                                       \
            LDS128(av, abase + (u32)((AB)*16384 + (s<<10) + (mt<<9)));       \
            afr[mt][0] = __float_as_uint(av.x);                              \
            afr[mt][1] = __float_as_uint(av.y);                              \
            afr[mt][2] = __float_as_uint(av.z);                              \
            afr[mt][3] = __float_as_uint(av.w);                              \
        }                                                                    \
        _Pragma("unroll")                                                    \
        for (int q = 0; q < 4; q++) {                                        \
            float4 bv;                                                       \
            LDS128(bv, sbase + (u32)((BB)*16384 + (s<<11) + (q<<9)));        \
            u32 b0 = __float_as_uint(bv.x), b1 = __float_as_uint(bv.y);      \
            u32 b2 = __float_as_uint(bv.z), b3 = __float_as_uint(bv.w);      \
            _Pragma("unroll")                                                \
            for (int mt = 0; mt < 2; mt++) {                                 \
                mma_tf32(acc[mt][2*q],     afr[mt], b0, b1);                 \
                mma_tf32(acc[mt][2*q + 1], afr[mt], b2, b3);                 \
            }                                                                \
        }                                                                    \
    }                                                                        \
} while(0)

#define CHUNK_C(BB, PH, AB, RID, FID) do {                                   \
    BAR_SYNC(RID, 384);                                                      \
    MBAR_WAIT(mb + (BB)*8, PH);                                              \
    CONSUME(BB, AB);                                                         \
    BAR_ARRIVE(FID, 384);                                                    \
} while(0)

__global__ void __launch_bounds__(384, 1)
fused_hmma_kernel(const float* __restrict__ atom_mask,
                  const float* __restrict__ gamma_,
                  const float* __restrict__ beta_,
                  float* __restrict__ out) {
    extern __shared__ char smc[];
    u32 sb = smem_u32(smc);
    float* sE = (float*)(smc);              // epilogue reuse of B region
    u32    mb = sb + SM_MBAR;

    int tid  = threadIdx.x;
    int wid  = tid >> 5, lane = tid & 31;
    int lq   = lane >> 2;    // 0..7
    int lr   = lane & 3;     // 0..3
    int row0 = blockIdx.x * BM;

    if (tid == 0) {
        MBARRIER_INIT(mb + 0,  1);
        MBARRIER_INIT(mb + 8,  1);
        MBARRIER_INIT(mb + 16, 1);
    }
    __syncthreads();

    float mu00 = (float)lr * 1.3333333333f;
    float mu01 = mu00 + 5.3333333333f;
    float mu10 = (float)(8 + lr) * 1.3333333333f;
    float mu11 = mu10 + 5.3333333333f;

    if (wid >= 8) {
        // ================= PRODUCER (warps 8-11) =================
        int pw = wid - 8;                    // handles wm = pw
        int gr  = row0 + (pw << 5) + lane;
        int b   = gr / (Lq * Kq);
        int rem = gr - b * (Lq * Kq);
        int i   = rem / Kq;
        int j   = g_Eidx[gr];
        int ii  = b * Lq + i, jj = b * Lq + j;
        const float* xi_b  = g_X2 + ii*42;
        const float* xj_b  = g_X2 + jj*42;
        const float* ami_b = atom_mask + ii*14;
        const float* amj_b = atom_mask + jj*14;
        float dpos = (float)(j - i);
        u32 afr_w = sb + SM_AFR + (u32)((pw << 12) + (lane << 4));

        // ---- issue B(0) ----
        if (tid == 256) {
            MBARRIER_EXPECT_TX(mb + 0, 16384);
            CP_BULK(sb + SM_SBF, g_Wfrag, mb + 0);
        }

        // ---- produce chunk 0 (posenc s<2; rbf P=0 for s>=2) into buf0 ----
        float Dl1, Cl1;
        {
            float dx = xi_b[0]-xj_b[0], dy = xi_b[1]-xj_b[1], dz = xi_b[2]-xj_b[2];
            Dl1 = sqrtf(dx*dx + dy*dy + dz*dz + 1e-6f);
            Cl1 = (1.f - ami_b[0]) * (1.f - amj_b[0]);
        }
        #pragma unroll
        for (int s = 0; s < 4; s++) {
            #pragma unroll
            for (int mt = 0; mt < 2; mt++) {
                int rbase = (mt << 4) + lq;
                u32 v0, v1, v2, v3;
                if (s < 2) {
                    float d0 = __shfl_sync(0xffffffffu, dpos, rbase);
                    float d1 = __shfl_sync(0xffffffffu, dpos, rbase + 8);
                    float sa0,ca0,sa1,ca1,sb0,cb0,sb1,cb1;
                    sincosf(d0 * c_freq[lr],     &sa0, &ca0);
                    sincosf(d1 * c_freq[lr],     &sa1, &ca1);
                    sincosf(d0 * c_freq[lr + 4], &sb0, &cb0);
                    sincosf(d1 * c_freq[lr + 4], &sb1, &cb1);
                    if (s == 0) { v0=f2tf32(ca0); v1=f2tf32(ca1); v2=f2tf32(cb0); v3=f2tf32(cb1); }
                    else        { v0=f2tf32(sa0); v1=f2tf32(sa1); v2=f2tf32(sb0); v3=f2tf32(sb1); }
                } else {
                    float D0 = __shfl_sync(0xffffffffu, Dl1, rbase);
                    float D1 = __shfl_sync(0xffffffffu, Dl1, rbase + 8);
                    float C0 = __shfl_sync(0xffffffffu, Cl1, rbase);
                    float C1 = __shfl_sync(0xffffffffu, Cl1, rbase + 8);
                    float m0 = (s == 2) ? mu00 : mu10;
                    float m1 = (s == 2) ? mu01 : mu11;
                    float t0 = D0 - m0, t1 = D1 - m0, t2 = D0 - m1, t3 = D1 - m1;
                    v0 = f2tf32(C0 * ex2f(t0*t0*-0.9233248262f));
                    v1 = f2tf32(C1 * ex2f(t1*t1*-0.9233248262f));
                    v2 = f2tf32(C0 * ex2f(t2*t2*-0.9233248262f));
                    v3 = f2tf32(C1 * ex2f(t3*t3*-0.9233248262f));
                }
                STS128(afr_w + (u32)((s << 10) + (mt << 9)), v0, v1, v2, v3);
            }
        }
        BAR_ARRIVE(1, 384);                  // ready[0]
        // ---- issue B(1) ----
        if (tid == 256) {
            MBARRIER_EXPECT_TX(mb + 8, 16384);
            CP_BULK(sb + SM_SBF + 16384, g_Wfrag + 4096, mb + 8);
        }

        int p0 = 0, q0 = 1, p1 = 0, q1 = 2;  // P0=1, P1=2 at k=1
        #pragma unroll 1
        for (int k = 1; k < NCHUNK; k++) {
            // per-lane D/co for this chunk's two pairs
            float Dl0, Cl0;
            {
                const float* xi = xi_b + p0*3;
                const float* xj = xj_b + q0*3;
                float dx = xi[0]-xj[0], dy = xi[1]-xj[1], dz = xi[2]-xj[2];
                Dl0 = sqrtf(dx*dx + dy*dy + dz*dz + 1e-6f);
                Cl0 = (1.f - ami_b[p0]) * (1.f - amj_b[q0]);
            }
            if (k < NCHUNK - 1) {
                const float* xi = xi_b + p1*3;
                const float* xj = xj_b + q1*3;
                float dx = xi[0]-xj[0], dy = xi[1]-xj[1], dz = xi[2]-xj[2];
                Dl1 = sqrtf(dx*dx + dy*dy + dz*dz + 1e-6f);
                Cl1 = (1.f - ami_b[p1]) * (1.f - amj_b[q1]);
            } else { Dl1 = 0.f; Cl1 = 0.f; }

            if (k >= 2) BAR_SYNC(3 + (k & 1), 384);   // free[k&1]
            // issue B(k+1)
            if (tid == 256 && k < NCHUNK - 1) {
                int nb = (k + 1) - ((k + 1) / 3) * 3;
                MBARRIER_EXPECT_TX(mb + nb*8, 16384);
                CP_BULK(sb + SM_SBF + (u32)(nb << 14),
                        g_Wfrag + ((size_t)(k + 1) << 12), mb + nb*8);
            }
            // produce afr(k) into buf k&1
            u32 ab_off = (u32)((k & 1) << 14);
            #pragma unroll
            for (int s = 0; s < 4; s++) {
                float Dsel = (s >= 2) ? Dl1 : Dl0;
                float Csel = (s >= 2) ? Cl1 : Cl0;
                float m0 = (s & 1) ? mu10 : mu00;
                float m1 = (s & 1) ? mu11 : mu01;
                #pragma unroll
                for (int mt = 0; mt < 2; mt++) {
                    int rbase = (mt << 4) + lq;
                    float D0 = __shfl_sync(0xffffffffu, Dsel, rbase);
                    float D1 = __shfl_sync(0xffffffffu, Dsel, rbase + 8);
                    float C0 = __shfl_sync(0xffffffffu, Csel, rbase);
                    float C1 = __shfl_sync(0xffffffffu, Csel, rbase + 8);
                    float t0 = D0 - m0, t1 = D1 - m0, t2 = D0 - m1, t3 = D1 - m1;
                    u32 v0 = f2tf32(C0 * ex2f(t0*t0*-0.9233248262f));
                    u32 v1 = f2tf32(C1 * ex2f(t1*t1*-0.9233248262f));
                    u32 v2 = f2tf32(C0 * ex2f(t2*t2*-0.9233248262f));
                    u32 v3 = f2tf32(C1 * ex2f(t3*t3*-0.9233248262f));
                    STS128(afr_w + ab_off + (u32)((s << 10) + (mt << 9)), v0, v1, v2, v3);
                }
            }
            BAR_ARRIVE(1 + (k & 1), 384);    // ready[k&1]
            q0 += 2; if (q0 >= 14) { q0 -= 14; p0 += 1; }
            q1 += 2; if (q1 >= 14) { q1 -= 14; p1 += 1; }
        }
        return;   // producers exit
    }

    // ================= CONSUMER (warps 0-7) =================
    int wm = wid & 3, wn = wid >> 2;
    u32 abase = sb + SM_AFR + (u32)((wm << 12) + (lane << 4));
    u32 sbase = sb + SM_SBF + (u32)((wn << 13) + (lane << 4));

    float acc[2][8][4];
    #pragma unroll
    for (int mt = 0; mt < 2; mt++)
        #pragma unroll
        for (int nt = 0; nt < 8; nt++)
            #pragma unroll
            for (int c = 0; c < 4; c++) acc[mt][nt][c] = 0.f;

    CHUNK_C(0, 0, 0, 1, 3);          // chunk 0
    #pragma unroll 1
    for (int kb = 0; kb < 16; kb++) {
        CHUNK_C(1, 0, 1, 2, 4);      // k = 6kb+1
        CHUNK_C(2, 0, 0, 1, 3);      // k = 6kb+2
        CHUNK_C(0, 1, 1, 2, 4);      // k = 6kb+3
        CHUNK_C(1, 1, 0, 1, 3);      // k = 6kb+4
        CHUNK_C(2, 1, 1, 2, 4);      // k = 6kb+5
        CHUNK_C(0, 0, 0, 1, 3);      // k = 6kb+6
    }
    CHUNK_C(1, 0, 1, 2, 4);          // k = 97
    CHUNK_C(2, 0, 0, 1, 3);          // k = 98

    // ================= epilogue (consumers only, named bar 5) ============
    float4 g4 = *(const float4*)&gamma_[lane << 2];
    float4 b4 = *(const float4*)&beta_ [lane << 2];

    #pragma unroll
    for (int h = 0; h < 2; h++) {
        BAR_SYNC(5, 256);
        if ((wm >> 1) == h) {
            #pragma unroll
            for (int mt = 0; mt < 2; mt++) {
                int rl = (wm << 5) + (mt << 4) + lq - (h << 6);
                #pragma unroll
                for (int nt = 0; nt < 8; nt++) {
                    int col = (wn << 6) + (nt << 3) + (lr << 1);
                    *(float2*)&sE[ rl      * ESTRIDE + col] =
                        make_float2(acc[mt][nt][0], acc[mt][nt][1]);
                    *(float2*)&sE[(rl + 8) * ESTRIDE + col] =
                        make_float2(acc[mt][nt][2], acc[mt][nt][3]);
                }
            }
        }
        BAR_SYNC(5, 256);
        #pragma unroll
        for (int rr = 0; rr < 8; rr++) {
            int rl = (wid << 3) + rr;
            float4 v = *(const float4*)&sE[rl * ESTRIDE + (lane << 2)];
            float s  = v.x + v.y + v.z + v.w;
            float sq2 = v.x*v.x + v.y*v.y + v.z*v.z + v.w*v.w;
            #pragma unroll
            for (int off = 16; off; off >>= 1) {
                s   += __shfl_xor_sync(0xffffffffu, s,   off);
                sq2 += __shfl_xor_sync(0xffffffffu, sq2, off);
            }
            float mean = s * (1.f/128.f);
            float var  = sq2 * (1.f/128.f) - mean * mean;
            float inv  = rsqrtf(var + 1e-5f);
            int gr = row0 + (h << 6) + rl;
            float4 o;
            o.x = (v.x - mean)*inv*g4.x + b4.x;
            o.y = (v.y - mean)*inv*g4.y + b4.y;
            o.z = (v.z - mean)*inv*g4.z + b4.z;
            o.w = (v.w - mean)*inv*g4.w + b4.w;
            *(float4*)&out[(size_t)gr * EFq + (lane << 2)] = o;
        }
    }
}

// =====================================================================
extern "C" void kernel_launch(void* const* d_in, const int* in_sizes, int n_in,
                              void* d_out, int out_size) {
    const float* X         = (const float*)d_in[0];
    const float* mask      = (const float*)d_in[1];
    const float* atom_mask = (const float*)d_in[4];
    const float* W         = (const float*)d_in[5];
    const float* gamma_    = (const float*)d_in[6];
    const float* beta_     = (const float*)d_in[7];
    float* out = (float*)d_out;

    float* out_tail = (out_size >= Mrows * (EFq + 1)) ? (out + (size_t)Mrows * EFq)
                                                      : nullptr;

    prep_kernel<<<PREP_GRID, 256>>>(X, mask, W, out_tail);

    cudaFuncSetAttribute(fused_hmma_kernel,
                         cudaFuncAttributeMaxDynamicSharedMemorySize, SM_TOTAL);
    fused_hmma_kernel<<<Mrows/BM, 384, SM_TOTAL>>>(atom_mask, gamma_, beta_, out);
}

// round 16
// speedup vs baseline: 2.2929x; 2.2929x over previous
#include <cuda_runtime.h>
#include <cuda_fp16.h>
#include <cstdint>
#include <math.h>

#define Bq 2
#define Lq 1024
#define Aq 14
#define Kq 30
#define EFq 128
#define EDGE_INq 3152
#define Mrows (Bq*Lq*Kq)      // 61440
#define BM 128
#define NCHUNK 99             // padded K = 3168

typedef uint32_t u32;

// ---- scratch ----
__device__ int g_Eidx[Mrows];
__device__ __align__(16) float g_X2[Bq*Lq*Aq*3];
__device__ __align__(16) u32 g_Wfrag[NCHUNK*2048];   // fp16-fragment-ordered W

__constant__ float c_freq[8] = {
    1.0f, 0.31622776601683794f, 0.1f, 0.031622776601683794f,
    0.01f, 0.0031622776601683794f, 0.001f, 0.00031622776601683794f
};

__device__ __forceinline__ float ex2f(float x) {
    float r; asm("ex2.approx.f32 %0, %1;" : "=f"(r) : "f"(x)); return r;
}
__device__ __forceinline__ u32 pack2(float lo, float hi) {
    __half2 h = __floats2half2_rn(lo, hi);
    return *(u32*)&h;
}
__device__ __forceinline__ u32 smem_u32(const void* p) {
    u32 a; asm("{ .reg .u64 t; cvta.to.shared.u64 t, %1; cvt.u32.u64 %0, t; }"
               : "=r"(a) : "l"(p));
    return a;
}
__device__ __forceinline__ void mma_f16(float* d, const u32* a, u32 b0, u32 b1) {
    asm volatile("mma.sync.aligned.m16n8k16.row.col.f32.f16.f16.f32 "
        "{%0,%1,%2,%3}, {%4,%5,%6,%7}, {%8,%9}, {%0,%1,%2,%3};"
        : "+f"(d[0]), "+f"(d[1]), "+f"(d[2]), "+f"(d[3])
        : "r"(a[0]), "r"(a[1]), "r"(a[2]), "r"(a[3]), "r"(b0), "r"(b1));
}
#define LDS128(v, addr) asm volatile("ld.shared.v4.f32 {%0,%1,%2,%3}, [%4];" \
    : "=f"(v.x), "=f"(v.y), "=f"(v.z), "=f"(v.w) : "r"(addr))
#define STS128(addr, a0, a1, a2, a3) asm volatile( \
    "st.shared.v4.b32 [%0], {%1,%2,%3,%4};" \
    :: "r"(addr), "r"(a0), "r"(a1), "r"(a2), "r"(a3) : "memory")
#define MBARRIER_INIT(a,c) asm volatile( \
    "mbarrier.init.shared.b64 [%0], %1;" :: "r"(a), "r"(c) : "memory")
#define MBARRIER_EXPECT_TX(a,b) asm volatile( \
    "mbarrier.arrive.expect_tx.shared.b64 _, [%0], %1;" :: "r"(a), "r"(b) : "memory")
#define CP_BULK(dst, src, mbar) asm volatile( \
    "cp.async.bulk.shared::cta.global.mbarrier::complete_tx::bytes [%0], [%1], %2, [%3];" \
    :: "r"(dst), "l"(src), "r"(8192), "r"(mbar) : "memory")
#define MBAR_WAIT(a, ph) asm volatile("{\n\t.reg .pred P;\n\tWL_%=:\n\t" \
    "mbarrier.try_wait.parity.acquire.cta.shared::cta.b64 P, [%0], %1, 0x989680;\n\t" \
    "@!P bra WL_%=;\n\t}" :: "r"(a), "r"(ph) : "memory")

// =====================================================================
// Kernel 1 (merged prep): topk | prepW(fp16 fragments) | buildX2
// =====================================================================
#define TOPK_BLOCKS  (Bq*Lq)                 // 2048
#define PREPW_BLOCKS ((NCHUNK*2048)/256)     // 792
#define BX2_BLOCKS   8
#define PREP_GRID    (TOPK_BLOCKS + PREPW_BLOCKS + BX2_BLOCKS)

__global__ void prep_kernel(const float* __restrict__ X,
                            const float* __restrict__ mask,
                            const float* __restrict__ W,
                            float* __restrict__ out_tail) {
    __shared__ float Da[Lq];
    __shared__ float svals[8];
    __shared__ int   sidx[8];
    __shared__ float sDmax;

    int bid = blockIdx.x;
    int tid = threadIdx.x;

    if (bid >= TOPK_BLOCKS) {
        if (bid < TOPK_BLOCKS + PREPW_BLOCKS) {
            // ---- prepW: per chunk u32 idx u(0-1)|lane(2-6)|q(7-8)|ks(9)|wn(10)
            // nt = 2q+(u>>1); e = u&1
            // n = wn*64 + nt*8 + (lane>>2)
            // c = k*32 + ks*16 + 2*(lane&3) + e*8     (pack W[n][c], W[n][c+1])
            int t = (bid - TOPK_BLOCKS) * 256 + tid;
            int u    = t & 3;
            int lane = (t >> 2) & 31;
            int q    = (t >> 7) & 3;
            int ks   = (t >> 9) & 1;
            int wn   = (t >> 10) & 1;
            int k    = t >> 11;
            int nt   = 2*q + (u >> 1);
            int e    = u & 1;
            int n = wn*64 + nt*8 + (lane >> 2);
            int c = k*32 + ks*16 + 2*(lane & 3) + e*8;
            float w0 = 0.f, w1 = 0.f;
            if (c < EDGE_INq) {
                w0 = W[(size_t)n * EDGE_INq + c];
                w1 = W[(size_t)n * EDGE_INq + c + 1];
            }
            __half2 h = __floats2half2_rn(w0, w1);
            g_Wfrag[t] = *(u32*)&h;
        } else {
            // ---- buildX2 ----
            int t = (bid - TOPK_BLOCKS - PREPW_BLOCKS) * 256 + tid;
            if (t < Bq * Lq) {
                const float* xr = X + (size_t)t * Aq * 3;
                float* o = g_X2 + (size_t)t * Aq * 3;
                #pragma unroll
                for (int a = 0; a < Aq*3; a++) o[a] = xr[a];
                float Nx = xr[0],  Ny = xr[1],  Nz = xr[2];
                float Cax= xr[3],  Cay= xr[4],  Caz= xr[5];
                float Cx = xr[6],  Cy = xr[7],  Cz = xr[8];
                float bx = Cax - Nx, by = Cay - Ny, bz = Caz - Nz;
                float cx = Cx - Cax, cy = Cy - Cay, cz = Cz - Caz;
                float ax = by*cz - bz*cy;
                float ay = bz*cx - bx*cz;
                float az = bx*cy - by*cx;
                o[12] = -0.58273431f*ax + 0.56802827f*bx - 0.54067466f*cx + Cax;
                o[13] = -0.58273431f*ay + 0.56802827f*by - 0.54067466f*cy + Cay;
                o[14] = -0.58273431f*az + 0.56802827f*bz - 0.54067466f*cz + Caz;
            }
        }
        return;
    }

    // ---- topk (unchanged) ----
    int bi  = bid;
    int b   = bi >> 10;
    int i   = bi & (Lq - 1);

    const float* Xb = X + (size_t)b * Lq * Aq * 3;
    float cx = Xb[(i*Aq+1)*3+0];
    float cy = Xb[(i*Aq+1)*3+1];
    float cz = Xb[(i*Aq+1)*3+2];
    float mi = mask[b*Lq + i];

    float lmax = 0.f;
    for (int j = tid; j < Lq; j += 256) {
        float dx = cx - Xb[(j*Aq+1)*3+0];
        float dy = cy - Xb[(j*Aq+1)*3+1];
        float dz = cz - Xb[(j*Aq+1)*3+2];
        float m2 = mi * mask[b*Lq + j];
        float D  = m2 * sqrtf(dx*dx + dy*dy + dz*dz + 1e-6f);
        Da[j] = D;
        lmax = fmaxf(lmax, D);
    }
    #pragma unroll
    for (int off = 16; off; off >>= 1)
        lmax = fmaxf(lmax, __shfl_xor_sync(0xffffffffu, lmax, off));
    if ((tid & 31) == 0) svals[tid >> 5] = lmax;
    __syncthreads();
    if (tid == 0) {
        float m = svals[0];
        for (int w = 1; w < 8; w++) m = fmaxf(m, svals[w]);
        sDmax = m;
    }
    __syncthreads();
    float Dmax = sDmax;
    for (int j = tid; j < Lq; j += 256) {
        float m2 = mi * mask[b*Lq + j];
        Da[j] += 2.f * (1.f - m2) * Dmax;
    }
    __syncthreads();

    for (int k = 0; k < Kq; k++) {
        float bv = 3.4e38f; int bj = 0x7fffffff;
        for (int j = tid; j < Lq; j += 256) {
            float v = Da[j];
            if (v < bv) { bv = v; bj = j; }
        }
        #pragma unroll
        for (int off = 16; off; off >>= 1) {
            float ov = __shfl_down_sync(0xffffffffu, bv, off);
            int   oj = __shfl_down_sync(0xffffffffu, bj, off);
            if (ov < bv || (ov == bv && oj < bj)) { bv = ov; bj = oj; }
        }
        if ((tid & 31) == 0) { svals[tid >> 5] = bv; sidx[tid >> 5] = bj; }
        __syncthreads();
        if (tid == 0) {
            for (int w = 1; w < 8; w++) {
                float v = svals[w]; int jj = sidx[w];
                if (v < bv || (v == bv && jj < bj)) { bv = v; bj = jj; }
            }
            int orow = bi * Kq + k;
            g_Eidx[orow] = bj;
            if (out_tail) out_tail[orow] = (float)bj;
            Da[bj] = 3.4e38f;
        }
        __syncthreads();
    }
}

// =====================================================================
// Kernel 2: fused featuregen + mma.sync m16n8k16 fp16 + LayerNorm
// R14 schedule: stage(k+1)+bulk B; sync; produce(k); sync; mbar-wait; consume
// B triple-buffered (8KB each); afr single-buffered (8KB)
// =====================================================================
#define SM_SBF   0          // 3 * 8192 = 24576 (B triple buffer)
#define SM_SD    24576      // 2 bufs * 256 f = 2048
#define SM_SCO   26624      // 2048
#define SM_DPOS  28672      // 512
#define SM_IIDX  29184      // 512
#define SM_JIDX  29696      // 512
#define SM_AFR   30208      // 4 wm x 2 ks x 2 mt x 512B = 8192
#define SM_MBAR  38400      // 3 x 8B
#define SM_TOTAL 38464
#define ESTRIDE  132        // epilogue reuses bytes [0, 33792)

// ---------- stage sD(k+1) + issue bulk B(k+1) into buffer NB ----------
#define STAGE_NEXT(NB) do {                                                  \
    float D = 0.f, co = 0.f;                                                 \
    if (sp < 14) {                                                           \
        const float* xi = xi_b + sp*3;                                       \
        const float* xj = xj_b + sq*3;                                       \
        float dx = xi[0]-xj[0], dy = xi[1]-xj[1], dz = xi[2]-xj[2];          \
        D  = sqrtf(dx*dx + dy*dy + dz*dz + 1e-6f);                          \
        co = (1.f - ami_b[sp]) * (1.f - amj_b[sq]);                          \
    }                                                                        \
    sDf [st_wr ^ 256] = D;                                                   \
    sCof[st_wr ^ 256] = co;                                                  \
    st_wr ^= 256;                                                            \
    sq += 2; if (sq >= 14) { sq -= 14; sp += 1; }                            \
    if (tid == 0) {                                                          \
        MBARRIER_EXPECT_TX(mb + (NB)*8, 8192);                               \
        CP_BULK(sb + SM_SBF + (NB)*8192, wsrc_n, mb + (NB)*8);               \
    }                                                                        \
    wsrc_n += 2048;                                                          \
} while(0)

// ---------- produce: warp (wm,wn) makes ks=wn fp16 fragments ----------
// a0={r(mu_a,D0),r(mu_b,D0)} a1={..D1} a2={r(mu_c,D0),r(mu_d,D0)} a3={..D1}
#define PRODUCE_RBF(SDB) do {                                                \
    _Pragma("unroll")                                                        \
    for (int mt = 0; mt < 2; mt++) {                                         \
        int ri = (SDB)*256 + sd_rd + (mt<<4);                                \
        float D0 = sDf[ri],     C0 = sCof[ri];                               \
        float D1 = sDf[ri + 8], C1 = sCof[ri + 8];                           \
        float ta0 = D0 - mu_a, tb0 = D0 - mu_b, tc0 = D0 - mu_c, td0 = D0 - mu_d; \
        float ta1 = D1 - mu_a, tb1 = D1 - mu_b, tc1 = D1 - mu_c, td1 = D1 - mu_d; \
        u32 a0 = pack2(C0*ex2f(ta0*ta0*-0.9233248262f), C0*ex2f(tb0*tb0*-0.9233248262f)); \
        u32 a1 = pack2(C1*ex2f(ta1*ta1*-0.9233248262f), C1*ex2f(tb1*tb1*-0.9233248262f)); \
        u32 a2 = pack2(C0*ex2f(tc0*tc0*-0.9233248262f), C0*ex2f(td0*td0*-0.9233248262f)); \
        u32 a3 = pack2(C1*ex2f(tc1*tc1*-0.9233248262f), C1*ex2f(td1*td1*-0.9233248262f)); \
        STS128(afr_st + (u32)(mt*512), a0, a1, a2, a3);                      \
    }                                                                        \
} while(0)

// ---------- consume chunk: B buffer BB ----------
#define CONSUME(BB) do {                                                     \
    _Pragma("unroll")                                                        \
    for (int ks = 0; ks < 2; ks++) {                                         \
        u32 afr[2][4];                                                       \
        _Pragma("unroll")                                                    \
        for (int mt = 0; mt < 2; mt++) {                                     \
            float4 av;                                                       \
            LDS128(av, abase + (u32)((ks<<10) + (mt<<9)));                   \
            afr[mt][0] = __float_as_uint(av.x);                              \
            afr[mt][1] = __float_as_uint(av.y);                              \
            afr[mt][2] = __float_as_uint(av.z);                              \
            afr[mt][3] = __float_as_uint(av.w);                              \
        }                                                                    \
        _Pragma("unroll")                                                    \
        for (int q = 0; q < 4; q++) {                                        \
            float4 bv;                                                       \
            LDS128(bv, sbase + (u32)((BB)*8192 + (ks<<11) + (q<<9)));        \
            u32 b0 = __float_as_uint(bv.x), b1 = __float_as_uint(bv.y);      \
            u32 b2 = __float_as_uint(bv.z), b3 = __float_as_uint(bv.w);      \
            _Pragma("unroll")                                                \
            for (int mt = 0; mt < 2; mt++) {                                 \
                mma_f16(acc[mt][2*q],     afr[mt], b0, b1);                  \
                mma_f16(acc[mt][2*q + 1], afr[mt], b2, b3);                  \
            }                                                                \
        }                                                                    \
    }                                                                        \
} while(0)

// WPH = literal mbarrier phase of buffer BB at this chunk
#define CHUNK_STD(SDB, BB, NB, WPH, HAS_NEXT) do {                           \
    if (HAS_NEXT) STAGE_NEXT(NB);                                            \
    __syncthreads();                                                         \
    PRODUCE_RBF(SDB);                                                        \
    __syncthreads();                                                         \
    MBAR_WAIT(mb + (BB)*8, WPH);                                             \
    CONSUME(BB);                                                             \
} while(0)

__global__ void __launch_bounds__(256, 2)
fused_hmma_kernel(const float* __restrict__ atom_mask,
                  const float* __restrict__ gamma_,
                  const float* __restrict__ beta_,
                  float* __restrict__ out) {
    extern __shared__ char smc[];
    u32 sb = smem_u32(smc);
    float* sE    = (float*)(smc);               // epilogue reuse
    float* sDf   = (float*)(smc + SM_SD);
    float* sCof  = (float*)(smc + SM_SCO);
    float* dposS = (float*)(smc + SM_DPOS);
    int*   iidx  = (int*)(smc + SM_IIDX);
    int*   jidx  = (int*)(smc + SM_JIDX);
    u32    mb    = sb + SM_MBAR;

    int tid  = threadIdx.x;
    int wid  = tid >> 5, lane = tid & 31;
    int wm   = wid & 3, wn = wid >> 2;
    int lq   = lane >> 2;    // 0..7
    int lr   = lane & 3;     // 0..3
    int row0 = blockIdx.x * BM;

    if (tid < BM) {
        int gr  = row0 + tid;
        int b   = gr / (Lq * Kq);
        int rem = gr - b * (Lq * Kq);
        int i   = rem / Kq;
        int j   = g_Eidx[gr];
        iidx[tid] = b * Lq + i;
        jidx[tid] = b * Lq + j;
        dposS[tid] = (float)(j - i);
    }
    if (tid == 0) {
        MBARRIER_INIT(mb + 0,  1);
        MBARRIER_INIT(mb + 8,  1);
        MBARRIER_INIT(mb + 16, 1);
    }
    __syncthreads();

    // ---- hoisted per-thread staging state ----
    int srow = tid & 127;
    int sl   = tid >> 7;
    const float* xi_b  = g_X2 + iidx[srow]*42;
    const float* xj_b  = g_X2 + jidx[srow]*42;
    const float* ami_b = atom_mask + iidx[srow]*14;
    const float* amj_b = atom_mask + jidx[srow]*14;
    int sp = 0, sq = 1 + sl;
    int st_wr = (sl << 7) + srow;

    // ---- stage chunk 0 into sD buf 0 (P = -1+sl) ----
    {
        float D = 0.f, co = 0.f;
        if (sl == 1) {
            float dx = xi_b[0]-xj_b[0], dy = xi_b[1]-xj_b[1], dz = xi_b[2]-xj_b[2];
            D  = sqrtf(dx*dx + dy*dy + dz*dz + 1e-6f);
            co = (1.f - ami_b[0]) * (1.f - amj_b[0]);
        }
        sDf [st_wr] = D;
        sCof[st_wr] = co;
        st_wr ^= 256;
    }
    st_wr ^= 256;        // STAGE_NEXT pre-toggles; leave at buf0 state

    // ---- B(0) bulk issue (buf0, phase 0) ----
    const u32* wsrc_n = g_Wfrag;
    if (tid == 0) {
        MBARRIER_EXPECT_TX(mb + 0, 8192);
        CP_BULK(sb + SM_SBF, wsrc_n, mb + 0);
    }
    wsrc_n += 2048;      // -> chunk 1

    // ---- hoisted producer/consumer bases ----
    int sd_rd   = (wn << 7) + (wm << 5) + lq;
    u32 afr_st  = sb + SM_AFR + (u32)((wm << 11) + (wn << 10) + (lane << 4));
    u32 abase   = sb + SM_AFR + (u32)((wm << 11) + (lane << 4));
    u32 sbase   = sb + SM_SBF + (u32)((wn << 12) + (lane << 4));
    // rbf mus for this thread: r = 2lr, 2lr+1, 2lr+8, 2lr+9
    float mu_a = (float)(2*lr) * 1.3333333333f;
    float mu_b = mu_a + 1.3333333333f;
    float mu_c = mu_a + 10.666666667f;
    float mu_d = mu_c + 1.3333333333f;

    float acc[2][8][4];
    #pragma unroll
    for (int mt = 0; mt < 2; mt++)
        #pragma unroll
        for (int nt = 0; nt < 8; nt++)
            #pragma unroll
            for (int c = 0; c < 4; c++) acc[mt][nt][c] = 0.f;

    // ================= chunk 0 (posenc in ks=0 / rbf P=0 in ks=1) ========
    {
        STAGE_NEXT(1);                       // sD buf1, B(1) -> buf1 (ph0)
        __syncthreads();
        if (wn == 0) {
            // posenc: features 2lr,2lr+1 -> cos(freq[2lr..]), +8 -> sin
            float f0 = c_freq[2*lr], f1 = c_freq[2*lr + 1];
            #pragma unroll
            for (int mt = 0; mt < 2; mt++) {
                int r0 = (wm << 5) + (mt << 4) + lq;
                float d0 = dposS[r0], d1 = dposS[r0 + 8];
                float s00, c00, s01, c01, s10, c10, s11, c11;
                sincosf(d0 * f0, &s00, &c00);
                sincosf(d0 * f1, &s01, &c01);
                sincosf(d1 * f0, &s10, &c10);
                sincosf(d1 * f1, &s11, &c11);
                u32 a0 = pack2(c00, c01);
                u32 a1 = pack2(c10, c11);
                u32 a2 = pack2(s00, s01);
                u32 a3 = pack2(s10, s11);
                STS128(afr_st + (u32)(mt*512), a0, a1, a2, a3);
            }
        } else {
            PRODUCE_RBF(0);                  // pair P=0 (sD buf0, l=1=wn)
        }
        __syncthreads();
        MBAR_WAIT(mb + 0, 0);
        CONSUME(0);
    }

    // ================= chunks 1..96 : 16 x 6 unrolled =================
    #pragma unroll 1
    for (int kb = 0; kb < 16; kb++) {
        CHUNK_STD(1, 1, 2, 0, 1);   // k = 6kb+1
        CHUNK_STD(0, 2, 0, 0, 1);   // k = 6kb+2
        CHUNK_STD(1, 0, 1, 1, 1);   // k = 6kb+3
        CHUNK_STD(0, 1, 2, 1, 1);   // k = 6kb+4
        CHUNK_STD(1, 2, 0, 1, 1);   // k = 6kb+5
        CHUNK_STD(0, 0, 1, 0, 1);   // k = 6kb+6
    }
    // ================= chunks 97, 98 =================
    CHUNK_STD(1, 1, 2, 0, 1);       // k = 97 (stages 98; sp<14 guards)
    CHUNK_STD(0, 2, 0, 0, 0);       // k = 98 (no next)

    // ================= epilogue: 2 halves of 64 rows =================
    float4 g4 = *(const float4*)&gamma_[lane << 2];
    float4 b4 = *(const float4*)&beta_ [lane << 2];

    #pragma unroll
    for (int h = 0; h < 2; h++) {
        __syncthreads();
        if ((wm >> 1) == h) {
            #pragma unroll
            for (int mt = 0; mt < 2; mt++) {
                int rl = (wm << 5) + (mt << 4) + lq - (h << 6);
                #pragma unroll
                for (int nt = 0; nt < 8; nt++) {
                    int col = (wn << 6) + (nt << 3) + (lr << 1);
                    *(float2*)&sE[ rl      * ESTRIDE + col] =
                        make_float2(acc[mt][nt][0], acc[mt][nt][1]);
                    *(float2*)&sE[(rl + 8) * ESTRIDE + col] =
                        make_float2(acc[mt][nt][2], acc[mt][nt][3]);
                }
            }
        }
        __syncthreads();
        #pragma unroll
        for (int rr = 0; rr < 8; rr++) {
            int rl = (wid << 3) + rr;
            float4 v = *(const float4*)&sE[rl * ESTRIDE + (lane << 2)];
            float s  = v.x + v.y + v.z + v.w;
            float sq2 = v.x*v.x + v.y*v.y + v.z*v.z + v.w*v.w;
            #pragma unroll
            for (int off = 16; off; off >>= 1) {
                s   += __shfl_xor_sync(0xffffffffu, s,   off);
                sq2 += __shfl_xor_sync(0xffffffffu, sq2, off);
            }
            float mean = s * (1.f/128.f);
            float var  = sq2 * (1.f/128.f) - mean * mean;
            float inv  = rsqrtf(var + 1e-5f);
            int gr = row0 + (h << 6) + rl;
            float4 o;
            o.x = (v.x - mean)*inv*g4.x + b4.x;
            o.y = (v.y - mean)*inv*g4.y + b4.y;
            o.z = (v.z - mean)*inv*g4.z + b4.z;
            o.w = (v.w - mean)*inv*g4.w + b4.w;
            *(float4*)&out[(size_t)gr * EFq + (lane << 2)] = o;
        }
    }
}

// =====================================================================
extern "C" void kernel_launch(void* const* d_in, const int* in_sizes, int n_in,
                              void* d_out, int out_size) {
    const float* X         = (const float*)d_in[0];
    const float* mask      = (const float*)d_in[1];
    const float* atom_mask = (const float*)d_in[4];
    const float* W         = (const float*)d_in[5];
    const float* gamma_    = (const float*)d_in[6];
    const float* beta_     = (const float*)d_in[7];
    float* out = (float*)d_out;

    float* out_tail = (out_size >= Mrows * (EFq + 1)) ? (out + (size_t)Mrows * EFq)
                                                      : nullptr;

    prep_kernel<<<PREP_GRID, 256>>>(X, mask, W, out_tail);

    cudaFuncSetAttribute(fused_hmma_kernel,
                         cudaFuncAttributeMaxDynamicSharedMemorySize, SM_TOTAL);
    fused_hmma_kernel<<<Mrows/BM, 256, SM_TOTAL>>>(atom_mask, gamma_, beta_, out);
}